// round 4
// baseline (speedup 1.0000x reference)
#include <cuda_runtime.h>
#include <math.h>

#define BB 4
#define SS 2048
#define DD 1024
#define HH 16
#define DH 64

// Scratch (allocation-free rule: __device__ globals)
__device__ float g_qkv[(size_t)BB * SS * 3 * DD];   // [B,S,3D]
__device__ float g_att[(size_t)BB * SS * DD];       // [B,S,D]

// ---------------------------------------------------------------------------
// SGEMM  C[M,N] = A[M,K] * W[N,K]^T (+ bias)
// BM=128, BN=128, BK=8, 256 threads, 8x8 register tile per thread.
// Assumes M%128==0, N%128==0, K%8==0 (true for all our shapes).
// ---------------------------------------------------------------------------
__global__ __launch_bounds__(256)
void sgemm_nt(const float* __restrict__ A, const float* __restrict__ W,
              const float* __restrict__ bias, float* __restrict__ C,
              int N, int K) {
    __shared__ float As[8][132];   // [k][m] transposed
    __shared__ float Bs[8][132];   // [k][n] transposed

    const int tid = threadIdx.x;
    const int tx = tid & 15;       // 0..15 -> n groups of 8
    const int ty = tid >> 4;       // 0..15 -> m groups of 8
    const int m0 = blockIdx.y * 128;
    const int n0 = blockIdx.x * 128;

    const int lr = tid >> 1;           // 0..127 row within tile
    const int lk = (tid & 1) * 4;      // 0 or 4

    float acc[8][8];
#pragma unroll
    for (int i = 0; i < 8; i++)
#pragma unroll
        for (int j = 0; j < 8; j++) acc[i][j] = 0.f;

    // prefetch first tile
    float4 av = *(const float4*)(A + (size_t)(m0 + lr) * K + lk);
    float4 bv = *(const float4*)(W + (size_t)(n0 + lr) * K + lk);

    for (int k0 = 0; k0 < K; k0 += 8) {
        __syncthreads();   // previous compute done
        As[lk + 0][lr] = av.x; As[lk + 1][lr] = av.y;
        As[lk + 2][lr] = av.z; As[lk + 3][lr] = av.w;
        Bs[lk + 0][lr] = bv.x; Bs[lk + 1][lr] = bv.y;
        Bs[lk + 2][lr] = bv.z; Bs[lk + 3][lr] = bv.w;
        __syncthreads();

        if (k0 + 8 < K) {  // prefetch next tile while computing
            av = *(const float4*)(A + (size_t)(m0 + lr) * K + k0 + 8 + lk);
            bv = *(const float4*)(W + (size_t)(n0 + lr) * K + k0 + 8 + lk);
        }

#pragma unroll
        for (int k = 0; k < 8; k++) {
            float4 a0 = *(const float4*)&As[k][ty * 8];
            float4 a1 = *(const float4*)&As[k][ty * 8 + 4];
            float4 b0 = *(const float4*)&Bs[k][tx * 8];
            float4 b1 = *(const float4*)&Bs[k][tx * 8 + 4];
            float af[8] = {a0.x, a0.y, a0.z, a0.w, a1.x, a1.y, a1.z, a1.w};
            float bf[8] = {b0.x, b0.y, b0.z, b0.w, b1.x, b1.y, b1.z, b1.w};
#pragma unroll
            for (int i = 0; i < 8; i++)
#pragma unroll
                for (int j = 0; j < 8; j++)
                    acc[i][j] = fmaf(af[i], bf[j], acc[i][j]);
        }
    }

#pragma unroll
    for (int i = 0; i < 8; i++) {
        const int row = m0 + ty * 8 + i;
        float* crow = C + (size_t)row * N + n0 + tx * 8;
#pragma unroll
        for (int jj = 0; jj < 8; jj += 4) {
            float4 v = make_float4(acc[i][jj], acc[i][jj + 1],
                                   acc[i][jj + 2], acc[i][jj + 3]);
            if (bias) {
                const float* bp = bias + n0 + tx * 8 + jj;
                v.x += bp[0]; v.y += bp[1]; v.z += bp[2]; v.w += bp[3];
            }
            *(float4*)(crow + jj) = v;
        }
    }
}

// ---------------------------------------------------------------------------
// Flash attention, fp32. One block per (b, h, 64-query tile).
// Br=Bc=64, 128 threads: ty=tid/16 (8 row-groups of 8), tx=tid%16 (col groups of 4).
// Qs/Ks are d-major in smem for float4 outer-product loads; online softmax with
// 16-lane shfl reductions; P through smem for the PV stage.
// ---------------------------------------------------------------------------
#define FPAD 68
#define FSM_TILE (64 * FPAD)

__global__ __launch_bounds__(128)
void flash_attn(const float* __restrict__ qkv, float* __restrict__ out) {
    extern __shared__ float sm[];
    float* Qs = sm;                 // [d][r]
    float* Ks = sm + FSM_TILE;      // [d][c]
    float* Vs = sm + 2 * FSM_TILE;  // [c][d]
    float* Ps = sm + 3 * FSM_TILE;  // [r][c]

    const int tid = threadIdx.x;
    const int tx = tid & 15;
    const int ty = tid >> 4;
    const int qt = blockIdx.x;
    const int h  = blockIdx.y;
    const int b  = blockIdx.z;

    const size_t base = (size_t)b * SS * 3 * DD + (size_t)h * DH;
    const float* qb = qkv + base;
    const float* kb = qkv + base + DD;
    const float* vb = qkv + base + 2 * DD;

    const float scale = 0.125f;  // 1/sqrt(64)

    // load Q tile (scaled), transposed to [d][r]
    for (int t = tid; t < 1024; t += 128) {
        const int r  = t >> 4;
        const int d4 = (t & 15) * 4;
        float4 q4 = *(const float4*)(qb + (size_t)(qt * 64 + r) * (3 * DD) + d4);
        Qs[(d4 + 0) * FPAD + r] = q4.x * scale;
        Qs[(d4 + 1) * FPAD + r] = q4.y * scale;
        Qs[(d4 + 2) * FPAD + r] = q4.z * scale;
        Qs[(d4 + 3) * FPAD + r] = q4.w * scale;
    }

    float acc[8][4];
    float mrow[8], lrow[8];
#pragma unroll
    for (int i = 0; i < 8; i++) {
        mrow[i] = -1e30f; lrow[i] = 0.f;
#pragma unroll
        for (int j = 0; j < 4; j++) acc[i][j] = 0.f;
    }
    __syncthreads();

    for (int kt = 0; kt < SS / 64; kt++) {
        // load K (transposed to [d][c]) and V ([c][d])
        for (int t = tid; t < 1024; t += 128) {
            const int c  = t >> 4;
            const int d4 = (t & 15) * 4;
            const size_t gofs = (size_t)(kt * 64 + c) * (3 * DD) + d4;
            float4 k4 = *(const float4*)(kb + gofs);
            Ks[(d4 + 0) * FPAD + c] = k4.x;
            Ks[(d4 + 1) * FPAD + c] = k4.y;
            Ks[(d4 + 2) * FPAD + c] = k4.z;
            Ks[(d4 + 3) * FPAD + c] = k4.w;
            float4 v4 = *(const float4*)(vb + gofs);
            *(float4*)(Vs + c * FPAD + d4) = v4;
        }
        __syncthreads();

        // S = (Q*scale) @ K^T : 8x4 per thread
        float s[8][4];
#pragma unroll
        for (int i = 0; i < 8; i++)
#pragma unroll
            for (int j = 0; j < 4; j++) s[i][j] = 0.f;

#pragma unroll 8
        for (int d = 0; d < 64; d++) {
            float4 kf = *(const float4*)(Ks + d * FPAD + tx * 4);
            float4 qa = *(const float4*)(Qs + d * FPAD + ty * 8);
            float4 qc = *(const float4*)(Qs + d * FPAD + ty * 8 + 4);
            float qf[8] = {qa.x, qa.y, qa.z, qa.w, qc.x, qc.y, qc.z, qc.w};
#pragma unroll
            for (int i = 0; i < 8; i++) {
                s[i][0] = fmaf(qf[i], kf.x, s[i][0]);
                s[i][1] = fmaf(qf[i], kf.y, s[i][1]);
                s[i][2] = fmaf(qf[i], kf.z, s[i][2]);
                s[i][3] = fmaf(qf[i], kf.w, s[i][3]);
            }
        }

        // online softmax (row reductions across the 16 tx lanes)
#pragma unroll
        for (int i = 0; i < 8; i++) {
            float tm = fmaxf(fmaxf(s[i][0], s[i][1]), fmaxf(s[i][2], s[i][3]));
#pragma unroll
            for (int msk = 8; msk >= 1; msk >>= 1)
                tm = fmaxf(tm, __shfl_xor_sync(0xffffffffu, tm, msk));
            const float mnew = fmaxf(mrow[i], tm);
            const float alpha = __expf(mrow[i] - mnew);
            const float p0 = __expf(s[i][0] - mnew);
            const float p1 = __expf(s[i][1] - mnew);
            const float p2 = __expf(s[i][2] - mnew);
            const float p3 = __expf(s[i][3] - mnew);
            float rs = p0 + p1 + p2 + p3;
#pragma unroll
            for (int msk = 8; msk >= 1; msk >>= 1)
                rs += __shfl_xor_sync(0xffffffffu, rs, msk);
            lrow[i] = lrow[i] * alpha + rs;
            mrow[i] = mnew;
            acc[i][0] *= alpha; acc[i][1] *= alpha;
            acc[i][2] *= alpha; acc[i][3] *= alpha;
            *(float4*)(Ps + (ty * 8 + i) * FPAD + tx * 4) =
                make_float4(p0, p1, p2, p3);
        }
        __syncthreads();

        // O += P @ V : each thread accumulates 8 rows x 4 dims
#pragma unroll 8
        for (int j = 0; j < 64; j++) {
            float4 vf = *(const float4*)(Vs + j * FPAD + tx * 4);
#pragma unroll
            for (int i = 0; i < 8; i++) {
                const float pv = Ps[(ty * 8 + i) * FPAD + j];
                acc[i][0] = fmaf(pv, vf.x, acc[i][0]);
                acc[i][1] = fmaf(pv, vf.y, acc[i][1]);
                acc[i][2] = fmaf(pv, vf.z, acc[i][2]);
                acc[i][3] = fmaf(pv, vf.w, acc[i][3]);
            }
        }
        __syncthreads();   // before next tile overwrites Ks/Vs
    }

    // normalize + write [B,S,D] layout
#pragma unroll
    for (int i = 0; i < 8; i++) {
        const float inv = 1.0f / lrow[i];
        const int sq = qt * 64 + ty * 8 + i;
        float4 o = make_float4(acc[i][0] * inv, acc[i][1] * inv,
                               acc[i][2] * inv, acc[i][3] * inv);
        *(float4*)(out + ((size_t)b * SS + sq) * DD + h * DH + tx * 4) = o;
    }
}

// ---------------------------------------------------------------------------
extern "C" void kernel_launch(void* const* d_in, const int* in_sizes, int n_in,
                              void* d_out, int out_size) {
    const float* x     = (const float*)d_in[0];   // [4,2048,1024]
    const float* w_in  = (const float*)d_in[1];   // [3072,1024]
    const float* w_out = (const float*)d_in[2];   // [1024,1024]
    const float* b_out = (const float*)d_in[3];   // [1024]
    float* out = (float*)d_out;                   // [4,2048,1024]

    float *qkv, *att;
    cudaGetSymbolAddress((void**)&qkv, g_qkv);
    cudaGetSymbolAddress((void**)&att, g_att);

    static int smem_set = 0;
    const int FLASH_SMEM = 4 * FSM_TILE * (int)sizeof(float);  // 69632
    if (!smem_set) {
        cudaFuncSetAttribute(flash_attn,
                             cudaFuncAttributeMaxDynamicSharedMemorySize,
                             FLASH_SMEM);
        smem_set = 1;
    }

    // 1) QKV projection: [8192,3072] = x[8192,1024] @ w_in^T
    sgemm_nt<<<dim3(3 * DD / 128, BB * SS / 128), 256>>>(
        x, w_in, nullptr, qkv, 3 * DD, DD);

    // 2) attention
    flash_attn<<<dim3(SS / 64, HH, BB), 128, FLASH_SMEM>>>(qkv, att);

    // 3) output projection + bias
    sgemm_nt<<<dim3(DD / 128, BB * SS / 128), 256>>>(
        att, w_out, b_out, out, DD, DD);
}

// round 6
// speedup vs baseline: 2.1608x; 2.1608x over previous
#include <cuda_runtime.h>
#include <cuda_bf16.h>
#include <cstdint>
#include <math.h>

#define BB 4
#define SS 2048
#define DD 1024
#define HH 16
#define DH 64
#define KP 3072            // split-K: 3 * DD
#define NITER (KP / 64)    // 48 chunks of 64 bf16

// ---------------------------------------------------------------------------
// Scratch (__device__ globals: allocation-free rule)
// ---------------------------------------------------------------------------
__device__ float         g_qkv[(size_t)BB * SS * 3 * DD];   // fp32 qkv [B,S,3D]
__device__ __nv_bfloat16 g_A1[(size_t)BB * SS * KP];        // x split    [hi|hi|lo]
__device__ __nv_bfloat16 g_W1[(size_t)3 * DD * KP];         // w_in split [hi|lo|hi]
__device__ __nv_bfloat16 g_A2[(size_t)BB * SS * KP];        // attn out   [hi|hi|lo]
__device__ __nv_bfloat16 g_W2[(size_t)DD * KP];             // w_out      [hi|lo|hi]

// ---------------------------------------------------------------------------
// family-safe PTX helpers (sm_80+ instructions only)
// ---------------------------------------------------------------------------
__device__ __forceinline__ uint32_t smem_to_u32(const void* p) {
    uint32_t a;
    asm("{ .reg .u64 t; cvta.to.shared.u64 t, %1; cvt.u32.u64 %0, t; }"
        : "=r"(a) : "l"(p));
    return a;
}
#define CP_ASYNC16(dst, src) \
    asm volatile("cp.async.cg.shared.global [%0], [%1], 16;\n" \
                 :: "r"(dst), "l"(src))
#define CP_COMMIT() asm volatile("cp.async.commit_group;\n" ::: "memory")
#define CP_WAIT(n)  asm volatile("cp.async.wait_group %0;\n" :: "n"(n) : "memory")

__device__ __forceinline__ void ldsm4(uint32_t& r0, uint32_t& r1,
                                      uint32_t& r2, uint32_t& r3, uint32_t addr) {
    asm volatile("ldmatrix.sync.aligned.m8n8.x4.shared.b16 {%0,%1,%2,%3}, [%4];\n"
                 : "=r"(r0), "=r"(r1), "=r"(r2), "=r"(r3) : "r"(addr));
}
__device__ __forceinline__ void mma16816(float* c, const uint32_t* a,
                                         uint32_t b0, uint32_t b1) {
    asm volatile(
        "mma.sync.aligned.m16n8k16.row.col.f32.bf16.bf16.f32 "
        "{%0,%1,%2,%3}, {%4,%5,%6,%7}, {%8,%9}, {%0,%1,%2,%3};\n"
        : "+f"(c[0]), "+f"(c[1]), "+f"(c[2]), "+f"(c[3])
        : "r"(a[0]), "r"(a[1]), "r"(a[2]), "r"(a[3]), "r"(b0), "r"(b1));
}

// ---------------------------------------------------------------------------
// fp32 -> bf16x3 split. dst row stride KP. slots: [hi | s1 | s2],
// loSlot==1 -> [hi|lo|hi] (weights), loSlot==2 -> [hi|hi|lo] (activations)
// ---------------------------------------------------------------------------
__device__ __forceinline__ uint32_t pk_bf2(__nv_bfloat16 a, __nv_bfloat16 b) {
    __nv_bfloat162 t; t.x = a; t.y = b;
    return *reinterpret_cast<uint32_t*>(&t);
}

__global__ void split3(const float* __restrict__ src, __nv_bfloat16* __restrict__ dst,
                       int rows, int loSlot) {
    int idx = blockIdx.x * blockDim.x + threadIdx.x;
    int total = rows * (DD / 4);
    if (idx >= total) return;
    int row = idx / (DD / 4);
    int c4  = (idx % (DD / 4)) * 4;
    float4 v = *(const float4*)(src + (size_t)row * DD + c4);
    float vv[4] = {v.x, v.y, v.z, v.w};
    __nv_bfloat16 h[4], l[4];
#pragma unroll
    for (int i = 0; i < 4; i++) {
        h[i] = __float2bfloat16_rn(vv[i]);
        l[i] = __float2bfloat16_rn(vv[i] - __bfloat162float(h[i]));
    }
    uint2 Hv = make_uint2(pk_bf2(h[0], h[1]), pk_bf2(h[2], h[3]));
    uint2 Lv = make_uint2(pk_bf2(l[0], l[1]), pk_bf2(l[2], l[3]));
    __nv_bfloat16* d0 = dst + (size_t)row * KP + c4;
    *(uint2*)(d0)          = Hv;
    *(uint2*)(d0 + DD)     = (loSlot == 1) ? Lv : Hv;
    *(uint2*)(d0 + 2 * DD) = (loSlot == 2) ? Lv : Hv;
}

// ---------------------------------------------------------------------------
// bf16 GEMM via mma.sync (HMMA):  C[M,Ntot] = A'[M,KP] @ W'[Ntot,KP]^T (+bias)
// 128x128 tile/CTA, 256 threads (8 warps, 64x32 warp tiles), BK=64,
// XOR-swizzled smem + cp.async double buffering.
// smem layout: buf0{A 16K, B 16K} buf1{A 16K, B 16K} = 64 KB
// ---------------------------------------------------------------------------
#define GSMEM 65536

__global__ __launch_bounds__(256)
void gemm_mma(const __nv_bfloat16* __restrict__ A,
              const __nv_bfloat16* __restrict__ Bw,
              const float* __restrict__ bias,
              float* __restrict__ C, int Ntot) {
    extern __shared__ char smem[];
    const uint32_t sb = smem_to_u32(smem);
    const int tid = threadIdx.x;
    const int lane = tid & 31, wid = tid >> 5;
    const int wm = wid & 1, wn = wid >> 1;          // 2 x 4 warp grid
    const int m0 = blockIdx.y * 128;
    const int n0 = blockIdx.x * 128;

    // --- loader mapping: 2 threads/row, 4x16B chunks each (row = 128B) ---
    const int lrow  = tid >> 1;
    const int jbase = (tid & 1) * 4;
    uint32_t soff[4];
#pragma unroll
    for (int j = 0; j < 4; j++)
        soff[j] = (uint32_t)lrow * 128 + (uint32_t)(((jbase + j) ^ (lrow & 7)) << 4);
    const char* gA = (const char*)(A  + (size_t)(m0 + lrow) * KP) + jbase * 16;
    const char* gB = (const char*)(Bw + (size_t)(n0 + lrow) * KP) + jbase * 16;

    float acc[4][4][4];
#pragma unroll
    for (int mt = 0; mt < 4; mt++)
#pragma unroll
        for (int nt = 0; nt < 4; nt++)
#pragma unroll
            for (int e = 0; e < 4; e++) acc[mt][nt][e] = 0.f;

    // per-lane ldmatrix address components
    const int a_row = wm * 64 + (lane & 15);
    const int a_cb  = lane >> 4;
    const int b_rowb = wn * 32 + (lane & 7) + ((lane >> 4) << 3);
    const int b_cb   = (lane >> 3) & 1;

    // --- prologue: fill both buffers ---
#pragma unroll
    for (int pi = 0; pi < 2; pi++) {
        const uint32_t base = sb + pi * 32768;
#pragma unroll
        for (int j = 0; j < 4; j++) {
            CP_ASYNC16(base + soff[j],         gA + (size_t)pi * 128 + j * 16);
            CP_ASYNC16(base + 16384 + soff[j], gB + (size_t)pi * 128 + j * 16);
        }
        CP_COMMIT();
    }

    for (int i = 0; i < NITER; i++) {
        if (i + 2 < NITER) { CP_WAIT(1); } else { CP_WAIT(0); }
        __syncthreads();

        const uint32_t aBase = sb + (i & 1) * 32768;
        const uint32_t bBase = aBase + 16384;
#pragma unroll
        for (int ks = 0; ks < 4; ks++) {
            uint32_t af[4][4], bf[2][4];
#pragma unroll
            for (int mt = 0; mt < 4; mt++) {
                const int row = a_row + mt * 16;
                const uint32_t addr =
                    aBase + row * 128 + (((ks * 2 + a_cb) ^ (row & 7)) << 4);
                ldsm4(af[mt][0], af[mt][1], af[mt][2], af[mt][3], addr);
            }
#pragma unroll
            for (int p = 0; p < 2; p++) {
                const int row = b_rowb + p * 16;
                const uint32_t addr =
                    bBase + row * 128 + (((ks * 2 + b_cb) ^ (row & 7)) << 4);
                ldsm4(bf[p][0], bf[p][1], bf[p][2], bf[p][3], addr);
            }
#pragma unroll
            for (int mt = 0; mt < 4; mt++)
#pragma unroll
                for (int nt = 0; nt < 4; nt++)
                    mma16816(acc[mt][nt], af[mt],
                             bf[nt >> 1][(nt & 1) * 2], bf[nt >> 1][(nt & 1) * 2 + 1]);
        }
        __syncthreads();

        if (i + 2 < NITER) {
            const uint32_t base = sb + (i & 1) * 32768;
#pragma unroll
            for (int j = 0; j < 4; j++) {
                CP_ASYNC16(base + soff[j],         gA + (size_t)(i + 2) * 128 + j * 16);
                CP_ASYNC16(base + 16384 + soff[j], gB + (size_t)(i + 2) * 128 + j * 16);
            }
            CP_COMMIT();
        }
    }

    // --- epilogue ---
#pragma unroll
    for (int mt = 0; mt < 4; mt++) {
        const int r = m0 + wm * 64 + mt * 16 + (lane >> 2);
#pragma unroll
        for (int nt = 0; nt < 4; nt++) {
            const int c = n0 + wn * 32 + nt * 8 + (lane & 3) * 2;
            float2 v0 = make_float2(acc[mt][nt][0], acc[mt][nt][1]);
            float2 v1 = make_float2(acc[mt][nt][2], acc[mt][nt][3]);
            if (bias) {
                const float b0v = bias[c], b1v = bias[c + 1];
                v0.x += b0v; v0.y += b1v;
                v1.x += b0v; v1.y += b1v;
            }
            *(float2*)(C + (size_t)r * Ntot + c)       = v0;
            *(float2*)(C + (size_t)(r + 8) * Ntot + c) = v1;
        }
    }
}

// ---------------------------------------------------------------------------
// Flash attention, fp32. Epilogue writes bf16 [hi|hi|lo] triple into g_A2.
// ---------------------------------------------------------------------------
#define FPAD 68
#define FSM_TILE (64 * FPAD)

__global__ __launch_bounds__(128)
void flash_attn(const float* __restrict__ qkv, __nv_bfloat16* __restrict__ outs) {
    extern __shared__ float sm[];
    float* Qs = sm;
    float* Ks = sm + FSM_TILE;
    float* Vs = sm + 2 * FSM_TILE;
    float* Ps = sm + 3 * FSM_TILE;

    const int tid = threadIdx.x;
    const int tx = tid & 15;
    const int ty = tid >> 4;
    const int qt = blockIdx.x;
    const int h  = blockIdx.y;
    const int b  = blockIdx.z;

    const size_t base = (size_t)b * SS * 3 * DD + (size_t)h * DH;
    const float* qb = qkv + base;
    const float* kb = qkv + base + DD;
    const float* vb = qkv + base + 2 * DD;
    const float scale = 0.125f;

    for (int t = tid; t < 1024; t += 128) {
        const int r  = t >> 4;
        const int d4 = (t & 15) * 4;
        float4 q4 = *(const float4*)(qb + (size_t)(qt * 64 + r) * (3 * DD) + d4);
        Qs[(d4 + 0) * FPAD + r] = q4.x * scale;
        Qs[(d4 + 1) * FPAD + r] = q4.y * scale;
        Qs[(d4 + 2) * FPAD + r] = q4.z * scale;
        Qs[(d4 + 3) * FPAD + r] = q4.w * scale;
    }

    float acc[8][4];
    float mrow[8], lrow[8];
#pragma unroll
    for (int i = 0; i < 8; i++) {
        mrow[i] = -1e30f; lrow[i] = 0.f;
#pragma unroll
        for (int j = 0; j < 4; j++) acc[i][j] = 0.f;
    }
    __syncthreads();

    for (int kt = 0; kt < SS / 64; kt++) {
        for (int t = tid; t < 1024; t += 128) {
            const int c  = t >> 4;
            const int d4 = (t & 15) * 4;
            const size_t gofs = (size_t)(kt * 64 + c) * (3 * DD) + d4;
            float4 k4 = *(const float4*)(kb + gofs);
            Ks[(d4 + 0) * FPAD + c] = k4.x;
            Ks[(d4 + 1) * FPAD + c] = k4.y;
            Ks[(d4 + 2) * FPAD + c] = k4.z;
            Ks[(d4 + 3) * FPAD + c] = k4.w;
            float4 v4 = *(const float4*)(vb + gofs);
            *(float4*)(Vs + c * FPAD + d4) = v4;
        }
        __syncthreads();

        float s[8][4];
#pragma unroll
        for (int i = 0; i < 8; i++)
#pragma unroll
            for (int j = 0; j < 4; j++) s[i][j] = 0.f;

#pragma unroll 8
        for (int d = 0; d < 64; d++) {
            float4 kf = *(const float4*)(Ks + d * FPAD + tx * 4);
            float4 qa = *(const float4*)(Qs + d * FPAD + ty * 8);
            float4 qc = *(const float4*)(Qs + d * FPAD + ty * 8 + 4);
            float qf[8] = {qa.x, qa.y, qa.z, qa.w, qc.x, qc.y, qc.z, qc.w};
#pragma unroll
            for (int i = 0; i < 8; i++) {
                s[i][0] = fmaf(qf[i], kf.x, s[i][0]);
                s[i][1] = fmaf(qf[i], kf.y, s[i][1]);
                s[i][2] = fmaf(qf[i], kf.z, s[i][2]);
                s[i][3] = fmaf(qf[i], kf.w, s[i][3]);
            }
        }

#pragma unroll
        for (int i = 0; i < 8; i++) {
            float tm = fmaxf(fmaxf(s[i][0], s[i][1]), fmaxf(s[i][2], s[i][3]));
#pragma unroll
            for (int msk = 8; msk >= 1; msk >>= 1)
                tm = fmaxf(tm, __shfl_xor_sync(0xffffffffu, tm, msk));
            const float mnew = fmaxf(mrow[i], tm);
            const float alpha = __expf(mrow[i] - mnew);
            const float p0 = __expf(s[i][0] - mnew);
            const float p1 = __expf(s[i][1] - mnew);
            const float p2 = __expf(s[i][2] - mnew);
            const float p3 = __expf(s[i][3] - mnew);
            float rs = p0 + p1 + p2 + p3;
#pragma unroll
            for (int msk = 8; msk >= 1; msk >>= 1)
                rs += __shfl_xor_sync(0xffffffffu, rs, msk);
            lrow[i] = lrow[i] * alpha + rs;
            mrow[i] = mnew;
            acc[i][0] *= alpha; acc[i][1] *= alpha;
            acc[i][2] *= alpha; acc[i][3] *= alpha;
            *(float4*)(Ps + (ty * 8 + i) * FPAD + tx * 4) =
                make_float4(p0, p1, p2, p3);
        }
        __syncthreads();

#pragma unroll 8
        for (int j = 0; j < 64; j++) {
            float4 vf = *(const float4*)(Vs + j * FPAD + tx * 4);
#pragma unroll
            for (int i = 0; i < 8; i++) {
                const float pv = Ps[(ty * 8 + i) * FPAD + j];
                acc[i][0] = fmaf(pv, vf.x, acc[i][0]);
                acc[i][1] = fmaf(pv, vf.y, acc[i][1]);
                acc[i][2] = fmaf(pv, vf.z, acc[i][2]);
                acc[i][3] = fmaf(pv, vf.w, acc[i][3]);
            }
        }
        __syncthreads();
    }

    // normalize + write bf16 [hi|hi|lo] directly into split activation buffer
#pragma unroll
    for (int i = 0; i < 8; i++) {
        const float inv = 1.0f / lrow[i];
        const int sq = qt * 64 + ty * 8 + i;
        float v[4] = {acc[i][0] * inv, acc[i][1] * inv,
                      acc[i][2] * inv, acc[i][3] * inv};
        __nv_bfloat16 hb[4], lb[4];
#pragma unroll
        for (int j = 0; j < 4; j++) {
            hb[j] = __float2bfloat16_rn(v[j]);
            lb[j] = __float2bfloat16_rn(v[j] - __bfloat162float(hb[j]));
        }
        uint2 Hv = make_uint2(pk_bf2(hb[0], hb[1]), pk_bf2(hb[2], hb[3]));
        uint2 Lv = make_uint2(pk_bf2(lb[0], lb[1]), pk_bf2(lb[2], lb[3]));
        __nv_bfloat16* d0 = outs + ((size_t)b * SS + sq) * KP + h * DH + tx * 4;
        *(uint2*)(d0)          = Hv;
        *(uint2*)(d0 + DD)     = Hv;
        *(uint2*)(d0 + 2 * DD) = Lv;
    }
}

// ---------------------------------------------------------------------------
extern "C" void kernel_launch(void* const* d_in, const int* in_sizes, int n_in,
                              void* d_out, int out_size) {
    const float* x     = (const float*)d_in[0];   // [4,2048,1024]
    const float* w_in  = (const float*)d_in[1];   // [3072,1024]
    const float* w_out = (const float*)d_in[2];   // [1024,1024]
    const float* b_out = (const float*)d_in[3];   // [1024]
    float* out = (float*)d_out;                   // [4,2048,1024]

    float *qkv;
    __nv_bfloat16 *A1, *W1, *A2, *W2;
    cudaGetSymbolAddress((void**)&qkv, g_qkv);
    cudaGetSymbolAddress((void**)&A1, g_A1);
    cudaGetSymbolAddress((void**)&W1, g_W1);
    cudaGetSymbolAddress((void**)&A2, g_A2);
    cudaGetSymbolAddress((void**)&W2, g_W2);

    static int attr_set = 0;
    const int FLASH_SMEM = 4 * FSM_TILE * (int)sizeof(float);  // 69632
    if (!attr_set) {
        cudaFuncSetAttribute(flash_attn,
                             cudaFuncAttributeMaxDynamicSharedMemorySize, FLASH_SMEM);
        cudaFuncSetAttribute(gemm_mma,
                             cudaFuncAttributeMaxDynamicSharedMemorySize, GSMEM);
        attr_set = 1;
    }

    const int rowsX = BB * SS;          // 8192
    // split inputs to bf16x3
    split3<<<(rowsX * (DD / 4) + 255) / 256, 256>>>(x, A1, rowsX, 2);
    split3<<<(3 * DD * (DD / 4) + 255) / 256, 256>>>(w_in, W1, 3 * DD, 1);
    split3<<<(DD * (DD / 4) + 255) / 256, 256>>>(w_out, W2, DD, 1);

    // 1) QKV projection on HMMA: [8192,3072] fp32 out
    gemm_mma<<<dim3(3 * DD / 128, rowsX / 128), 256, GSMEM>>>(
        A1, W1, nullptr, qkv, 3 * DD);

    // 2) attention (fp32), writes bf16x3 activation for stage 3
    flash_attn<<<dim3(SS / 64, HH, BB), 128, FLASH_SMEM>>>(qkv, A2);

    // 3) output projection + bias on HMMA
    gemm_mma<<<dim3(DD / 128, rowsX / 128), 256, GSMEM>>>(
        A2, W2, b_out, out, DD);
}

// round 7
// speedup vs baseline: 3.8993x; 1.8046x over previous
#include <cuda_runtime.h>
#include <cuda_bf16.h>
#include <cstdint>
#include <math.h>

#define BB 4
#define SS 2048
#define DD 1024
#define HH 16
#define DH 64
#define KP 3072            // split-K: 3 * DD
#define NITER (KP / 64)    // 48 chunks of 64 bf16

// ---------------------------------------------------------------------------
// Scratch (__device__ globals: allocation-free rule)
// ---------------------------------------------------------------------------
__device__ __nv_bfloat16 g_A1[(size_t)BB * SS * KP];        // x split    [hi|hi|lo]
__device__ __nv_bfloat16 g_W1[(size_t)3 * DD * KP];         // w_in split [hi|lo|hi]
__device__ __nv_bfloat16 g_A2[(size_t)BB * SS * KP];        // attn out   [hi|hi|lo]
__device__ __nv_bfloat16 g_W2[(size_t)DD * KP];             // w_out      [hi|lo|hi]
// per-head split QKV: [b][h][s][64]
__device__ __nv_bfloat16 g_Qh[(size_t)BB * HH * SS * DH];
__device__ __nv_bfloat16 g_Ql[(size_t)BB * HH * SS * DH];
__device__ __nv_bfloat16 g_Kh[(size_t)BB * HH * SS * DH];
__device__ __nv_bfloat16 g_Kl[(size_t)BB * HH * SS * DH];
__device__ __nv_bfloat16 g_Vh[(size_t)BB * HH * SS * DH];
__device__ __nv_bfloat16 g_Vl[(size_t)BB * HH * SS * DH];

// ---------------------------------------------------------------------------
// family-safe PTX helpers (sm_80+)
// ---------------------------------------------------------------------------
__device__ __forceinline__ uint32_t smem_to_u32(const void* p) {
    uint32_t a;
    asm("{ .reg .u64 t; cvta.to.shared.u64 t, %1; cvt.u32.u64 %0, t; }"
        : "=r"(a) : "l"(p));
    return a;
}
#define CP_ASYNC16(dst, src) \
    asm volatile("cp.async.cg.shared.global [%0], [%1], 16;\n" \
                 :: "r"(dst), "l"(src))
#define CP_COMMIT() asm volatile("cp.async.commit_group;\n" ::: "memory")
#define CP_WAIT(n)  asm volatile("cp.async.wait_group %0;\n" :: "n"(n) : "memory")

__device__ __forceinline__ void ldsm4(uint32_t& r0, uint32_t& r1,
                                      uint32_t& r2, uint32_t& r3, uint32_t addr) {
    asm volatile("ldmatrix.sync.aligned.m8n8.x4.shared.b16 {%0,%1,%2,%3}, [%4];\n"
                 : "=r"(r0), "=r"(r1), "=r"(r2), "=r"(r3) : "r"(addr));
}
__device__ __forceinline__ void ldsm4t(uint32_t* r, uint32_t addr) {
    asm volatile("ldmatrix.sync.aligned.m8n8.x4.trans.shared.b16 {%0,%1,%2,%3}, [%4];\n"
                 : "=r"(r[0]), "=r"(r[1]), "=r"(r[2]), "=r"(r[3]) : "r"(addr));
}
__device__ __forceinline__ void mma16816(float* c, const uint32_t* a,
                                         uint32_t b0, uint32_t b1) {
    asm volatile(
        "mma.sync.aligned.m16n8k16.row.col.f32.bf16.bf16.f32 "
        "{%0,%1,%2,%3}, {%4,%5,%6,%7}, {%8,%9}, {%0,%1,%2,%3};\n"
        : "+f"(c[0]), "+f"(c[1]), "+f"(c[2]), "+f"(c[3])
        : "r"(a[0]), "r"(a[1]), "r"(a[2]), "r"(a[3]), "r"(b0), "r"(b1));
}
__device__ __forceinline__ float exp2a(float x) {
    float r; asm("ex2.approx.f32 %0, %1;" : "=f"(r) : "f"(x)); return r;
}
// split (x0,x1) into packed bf16x2 hi + lo residual (lo halves of pair = x0)
__device__ __forceinline__ void split_pair(float x0, float x1,
                                           uint32_t& hi, uint32_t& lo) {
    uint32_t hp;
    asm("cvt.rn.bf16x2.f32 %0, %1, %2;" : "=r"(hp) : "f"(x1), "f"(x0));
    const float h0 = __uint_as_float(hp << 16);
    const float h1 = __uint_as_float(hp & 0xFFFF0000u);
    uint32_t lp;
    asm("cvt.rn.bf16x2.f32 %0, %1, %2;" : "=r"(lp) : "f"(x1 - h1), "f"(x0 - h0));
    hi = hp; lo = lp;
}
__device__ __forceinline__ uint32_t pk_bf2(__nv_bfloat16 a, __nv_bfloat16 b) {
    __nv_bfloat162 t; t.x = a; t.y = b;
    return *reinterpret_cast<uint32_t*>(&t);
}

// ---------------------------------------------------------------------------
// fp32 -> bf16x3 split (GEMM inputs). loSlot 1 = weights [hi|lo|hi],
// loSlot 2 = activations [hi|hi|lo].
// ---------------------------------------------------------------------------
__global__ void split3(const float* __restrict__ src, __nv_bfloat16* __restrict__ dst,
                       int rows, int loSlot) {
    int idx = blockIdx.x * blockDim.x + threadIdx.x;
    int total = rows * (DD / 4);
    if (idx >= total) return;
    int row = idx / (DD / 4);
    int c4  = (idx % (DD / 4)) * 4;
    float4 v = *(const float4*)(src + (size_t)row * DD + c4);
    float vv[4] = {v.x, v.y, v.z, v.w};
    __nv_bfloat16 h[4], l[4];
#pragma unroll
    for (int i = 0; i < 4; i++) {
        h[i] = __float2bfloat16_rn(vv[i]);
        l[i] = __float2bfloat16_rn(vv[i] - __bfloat162float(h[i]));
    }
    uint2 Hv = make_uint2(pk_bf2(h[0], h[1]), pk_bf2(h[2], h[3]));
    uint2 Lv = make_uint2(pk_bf2(l[0], l[1]), pk_bf2(l[2], l[3]));
    __nv_bfloat16* d0 = dst + (size_t)row * KP + c4;
    *(uint2*)(d0)          = Hv;
    *(uint2*)(d0 + DD)     = (loSlot == 1) ? Lv : Hv;
    *(uint2*)(d0 + 2 * DD) = (loSlot == 2) ? Lv : Hv;
}

// ---------------------------------------------------------------------------
// bf16 GEMM via mma.sync:  C = A'[M,KP] @ W'[Ntot,KP]^T
// splitMode 0: C fp32 (+bias).  splitMode 1: write per-head split Q/K/V
// (Q scaled by 0.125*log2e), no C write.
// ---------------------------------------------------------------------------
#define GSMEM 65536
#define QSC 0.18033688011112042f   // 0.125 * log2(e)

__global__ __launch_bounds__(256)
void gemm_mma(const __nv_bfloat16* __restrict__ A,
              const __nv_bfloat16* __restrict__ Bw,
              const float* __restrict__ bias,
              float* __restrict__ C, int Ntot, int splitMode,
              __nv_bfloat16* __restrict__ Qh, __nv_bfloat16* __restrict__ Ql,
              __nv_bfloat16* __restrict__ Kh, __nv_bfloat16* __restrict__ Kl,
              __nv_bfloat16* __restrict__ Vh, __nv_bfloat16* __restrict__ Vl) {
    extern __shared__ char smem[];
    const uint32_t sb = smem_to_u32(smem);
    const int tid = threadIdx.x;
    const int lane = tid & 31, wid = tid >> 5;
    const int wm = wid & 1, wn = wid >> 1;          // 2 x 4 warp grid
    const int m0 = blockIdx.y * 128;
    const int n0 = blockIdx.x * 128;

    const int lrow  = tid >> 1;
    const int jbase = (tid & 1) * 4;
    uint32_t soff[4];
#pragma unroll
    for (int j = 0; j < 4; j++)
        soff[j] = (uint32_t)lrow * 128 + (uint32_t)(((jbase + j) ^ (lrow & 7)) << 4);
    const char* gA = (const char*)(A  + (size_t)(m0 + lrow) * KP) + jbase * 16;
    const char* gB = (const char*)(Bw + (size_t)(n0 + lrow) * KP) + jbase * 16;

    float acc[4][4][4];
#pragma unroll
    for (int mt = 0; mt < 4; mt++)
#pragma unroll
        for (int nt = 0; nt < 4; nt++)
#pragma unroll
            for (int e = 0; e < 4; e++) acc[mt][nt][e] = 0.f;

    const int a_row = wm * 64 + (lane & 15);
    const int a_cb  = lane >> 4;
    const int b_rowb = wn * 32 + (lane & 7) + ((lane >> 4) << 3);
    const int b_cb   = (lane >> 3) & 1;

#pragma unroll
    for (int pi = 0; pi < 2; pi++) {
        const uint32_t base = sb + pi * 32768;
#pragma unroll
        for (int j = 0; j < 4; j++) {
            CP_ASYNC16(base + soff[j],         gA + (size_t)pi * 128 + j * 16);
            CP_ASYNC16(base + 16384 + soff[j], gB + (size_t)pi * 128 + j * 16);
        }
        CP_COMMIT();
    }

    for (int i = 0; i < NITER; i++) {
        if (i + 2 < NITER) { CP_WAIT(1); } else { CP_WAIT(0); }
        __syncthreads();

        const uint32_t aBase = sb + (i & 1) * 32768;
        const uint32_t bBase = aBase + 16384;
#pragma unroll
        for (int ks = 0; ks < 4; ks++) {
            uint32_t af[4][4], bf[2][4];
#pragma unroll
            for (int mt = 0; mt < 4; mt++) {
                const int row = a_row + mt * 16;
                const uint32_t addr =
                    aBase + row * 128 + (((ks * 2 + a_cb) ^ (row & 7)) << 4);
                ldsm4(af[mt][0], af[mt][1], af[mt][2], af[mt][3], addr);
            }
#pragma unroll
            for (int p = 0; p < 2; p++) {
                const int row = b_rowb + p * 16;
                const uint32_t addr =
                    bBase + row * 128 + (((ks * 2 + b_cb) ^ (row & 7)) << 4);
                ldsm4(bf[p][0], bf[p][1], bf[p][2], bf[p][3], addr);
            }
#pragma unroll
            for (int mt = 0; mt < 4; mt++)
#pragma unroll
                for (int nt = 0; nt < 4; nt++)
                    mma16816(acc[mt][nt], af[mt],
                             bf[nt >> 1][(nt & 1) * 2], bf[nt >> 1][(nt & 1) * 2 + 1]);
        }
        __syncthreads();

        if (i + 2 < NITER) {
            const uint32_t base = sb + (i & 1) * 32768;
#pragma unroll
            for (int j = 0; j < 4; j++) {
                CP_ASYNC16(base + soff[j],         gA + (size_t)(i + 2) * 128 + j * 16);
                CP_ASYNC16(base + 16384 + soff[j], gB + (size_t)(i + 2) * 128 + j * 16);
            }
            CP_COMMIT();
        }
    }

    if (splitMode) {
        // scatter into per-head hi/lo split arrays
#pragma unroll
        for (int mt = 0; mt < 4; mt++) {
            const int r = m0 + wm * 64 + mt * 16 + (lane >> 2);
#pragma unroll
            for (int nt = 0; nt < 4; nt++) {
                const int c = n0 + wn * 32 + nt * 8 + (lane & 3) * 2;
                const int sel = c >> 10;
                const int hh  = (c >> 6) & 15;
                const int d   = c & 63;
                __nv_bfloat16* dH = (sel == 0) ? Qh : (sel == 1) ? Kh : Vh;
                __nv_bfloat16* dL = (sel == 0) ? Ql : (sel == 1) ? Kl : Vl;
                const float sc = (sel == 0) ? QSC : 1.f;
#pragma unroll
                for (int hr = 0; hr < 2; hr++) {
                    const int row = r + hr * 8;
                    const int bb = row >> 11, ss = row & 2047;
                    const size_t idx =
                        (((size_t)(bb * HH + hh)) * SS + ss) * DH + d;
                    uint32_t hp, lp;
                    split_pair(acc[mt][nt][hr * 2] * sc,
                               acc[mt][nt][hr * 2 + 1] * sc, hp, lp);
                    *(uint32_t*)(dH + idx) = hp;
                    *(uint32_t*)(dL + idx) = lp;
                }
            }
        }
    } else {
#pragma unroll
        for (int mt = 0; mt < 4; mt++) {
            const int r = m0 + wm * 64 + mt * 16 + (lane >> 2);
#pragma unroll
            for (int nt = 0; nt < 4; nt++) {
                const int c = n0 + wn * 32 + nt * 8 + (lane & 3) * 2;
                float2 v0 = make_float2(acc[mt][nt][0], acc[mt][nt][1]);
                float2 v1 = make_float2(acc[mt][nt][2], acc[mt][nt][3]);
                if (bias) {
                    const float b0v = bias[c], b1v = bias[c + 1];
                    v0.x += b0v; v0.y += b1v;
                    v1.x += b0v; v1.y += b1v;
                }
                *(float2*)(C + (size_t)r * Ntot + c)       = v0;
                *(float2*)(C + (size_t)(r + 8) * Ntot + c) = v1;
            }
        }
    }
}

// ---------------------------------------------------------------------------
// Flash attention on mma.sync. Br=128, Bc=64, 8 warps.
// S = Qh*Kh + Ql*Kh + Qh*Kl ; O = Ph*Vh + Pl*Vh + Ph*Vl (bf16x3 both stages).
// Q pre-scaled by 0.125*log2e -> softmax via ex2.approx.
// smem: Qh 16K | Ql 16K | 2 x KV buf (Kh 8K | Kl 8K | Vh 8K | Vl 8K)
// ---------------------------------------------------------------------------
#define FSMEM 98304

__global__ __launch_bounds__(256, 2)
void flash_mma(const __nv_bfloat16* __restrict__ Qh, const __nv_bfloat16* __restrict__ Ql,
               const __nv_bfloat16* __restrict__ Kh, const __nv_bfloat16* __restrict__ Kl,
               const __nv_bfloat16* __restrict__ Vh, const __nv_bfloat16* __restrict__ Vl,
               __nv_bfloat16* __restrict__ outs) {
    extern __shared__ char smem[];
    const uint32_t sb = smem_to_u32(smem);
    const int tid = threadIdx.x, lane = tid & 31, wid = tid >> 5;
    const int qt = blockIdx.x, h = blockIdx.y, b = blockIdx.z;
    const size_t gq = ((size_t)(b * HH + h) * SS + (size_t)qt * 128) * DH;
    const size_t gk = (size_t)(b * HH + h) * SS * DH;

    // --- Q load: 128 rows x 8 chunks, hi + lo ---
    {
        const int row = tid >> 1;
        const int cb = (tid & 1) * 4;
        const char* ph = (const char*)(Qh + gq + (size_t)row * DH);
        const char* pl = (const char*)(Ql + gq + (size_t)row * DH);
#pragma unroll
        for (int j = 0; j < 4; j++) {
            const int ch = cb + j;
            const uint32_t so = row * 128 + ((ch ^ (row & 7)) << 4);
            CP_ASYNC16(sb + so,         ph + ch * 16);
            CP_ASYNC16(sb + 16384 + so, pl + ch * 16);
        }
    }
    const int kvrow = tid >> 2;
    const int kvcb  = (tid & 3) * 2;
    auto loadKV = [&](int kt, uint32_t bufb) {
        const size_t ro = gk + (size_t)(kt * 64 + kvrow) * DH;
#pragma unroll
        for (int j = 0; j < 2; j++) {
            const int ch = kvcb + j;
            const uint32_t so = kvrow * 128 + ((ch ^ (kvrow & 7)) << 4);
            CP_ASYNC16(bufb + so,         (const char*)(Kh + ro) + ch * 16);
            CP_ASYNC16(bufb + 8192 + so,  (const char*)(Kl + ro) + ch * 16);
            CP_ASYNC16(bufb + 16384 + so, (const char*)(Vh + ro) + ch * 16);
            CP_ASYNC16(bufb + 24576 + so, (const char*)(Vl + ro) + ch * 16);
        }
    };
    loadKV(0, sb + 32768); CP_COMMIT();
    loadKV(1, sb + 65536); CP_COMMIT();

    float s[8][4], o[8][4];
    float m0 = -100000.f, m1 = -100000.f, l0 = 0.f, l1 = 0.f;
#pragma unroll
    for (int t = 0; t < 8; t++)
#pragma unroll
        for (int e = 0; e < 4; e++) o[t][e] = 0.f;

    const int aRow   = wid * 16 + (lane & 15);
    const int aCb    = lane >> 4;
    const int kRowOf = (lane & 7) + ((lane >> 4) << 3);
    const int kCb    = (lane >> 3) & 1;
    const int vRowOf = (lane & 7) + (((lane >> 3) & 1) << 3);
    const int vCb    = lane >> 4;

    for (int kt = 0; kt < SS / 64; kt++) {
        if (kt + 2 < SS / 64) { CP_WAIT(1); } else { CP_WAIT(0); }
        __syncthreads();
        const uint32_t kb = sb + 32768 + (kt & 1) * 32768;

#pragma unroll
        for (int t = 0; t < 8; t++)
#pragma unroll
            for (int e = 0; e < 4; e++) s[t][e] = 0.f;

        // ---- S = Q*K^T (3 terms) ----
#pragma unroll
        for (int ks = 0; ks < 4; ks++) {
            uint32_t qf[4], ql[4];
            const uint32_t qa =
                sb + aRow * 128 + (((2 * ks + aCb) ^ (aRow & 7)) << 4);
            ldsm4(qf[0], qf[1], qf[2], qf[3], qa);
            ldsm4(ql[0], ql[1], ql[2], ql[3], qa + 16384);
#pragma unroll
            for (int np = 0; np < 4; np++) {
                const int krow = np * 16 + kRowOf;
                const uint32_t ka =
                    kb + krow * 128 + (((2 * ks + kCb) ^ (krow & 7)) << 4);
                uint32_t f[4];
                ldsm4(f[0], f[1], f[2], f[3], ka);          // Kh
                mma16816(s[2 * np],     qf, f[0], f[1]);
                mma16816(s[2 * np + 1], qf, f[2], f[3]);
                mma16816(s[2 * np],     ql, f[0], f[1]);
                mma16816(s[2 * np + 1], ql, f[2], f[3]);
                ldsm4(f[0], f[1], f[2], f[3], ka + 8192);   // Kl
                mma16816(s[2 * np],     qf, f[0], f[1]);
                mma16816(s[2 * np + 1], qf, f[2], f[3]);
            }
        }

        // ---- online softmax (rows r=lane>>2 and r+8) ----
        {
            float mx = fmaxf(s[0][0], s[0][1]);
#pragma unroll
            for (int t = 1; t < 8; t++) mx = fmaxf(mx, fmaxf(s[t][0], s[t][1]));
            mx = fmaxf(mx, __shfl_xor_sync(0xffffffffu, mx, 1));
            mx = fmaxf(mx, __shfl_xor_sync(0xffffffffu, mx, 2));
            const float mn = fmaxf(m0, mx);
            const float al = exp2a(m0 - mn);
            float sum = 0.f;
#pragma unroll
            for (int t = 0; t < 8; t++) {
                s[t][0] = exp2a(s[t][0] - mn);
                s[t][1] = exp2a(s[t][1] - mn);
                sum += s[t][0] + s[t][1];
            }
            sum += __shfl_xor_sync(0xffffffffu, sum, 1);
            sum += __shfl_xor_sync(0xffffffffu, sum, 2);
            l0 = l0 * al + sum; m0 = mn;
#pragma unroll
            for (int t = 0; t < 8; t++) { o[t][0] *= al; o[t][1] *= al; }
        }
        {
            float mx = fmaxf(s[0][2], s[0][3]);
#pragma unroll
            for (int t = 1; t < 8; t++) mx = fmaxf(mx, fmaxf(s[t][2], s[t][3]));
            mx = fmaxf(mx, __shfl_xor_sync(0xffffffffu, mx, 1));
            mx = fmaxf(mx, __shfl_xor_sync(0xffffffffu, mx, 2));
            const float mn = fmaxf(m1, mx);
            const float al = exp2a(m1 - mn);
            float sum = 0.f;
#pragma unroll
            for (int t = 0; t < 8; t++) {
                s[t][2] = exp2a(s[t][2] - mn);
                s[t][3] = exp2a(s[t][3] - mn);
                sum += s[t][2] + s[t][3];
            }
            sum += __shfl_xor_sync(0xffffffffu, sum, 1);
            sum += __shfl_xor_sync(0xffffffffu, sum, 2);
            l1 = l1 * al + sum; m1 = mn;
#pragma unroll
            for (int t = 0; t < 8; t++) { o[t][2] *= al; o[t][3] *= al; }
        }

        // ---- O += P*V (3 terms); P frags built in-register from S ----
#pragma unroll
        for (int ks = 0; ks < 4; ks++) {
            uint32_t ph[4], pl[4];
            split_pair(s[2 * ks][0],     s[2 * ks][1],     ph[0], pl[0]);
            split_pair(s[2 * ks][2],     s[2 * ks][3],     ph[1], pl[1]);
            split_pair(s[2 * ks + 1][0], s[2 * ks + 1][1], ph[2], pl[2]);
            split_pair(s[2 * ks + 1][2], s[2 * ks + 1][3], ph[3], pl[3]);
#pragma unroll
            for (int np = 0; np < 4; np++) {
                const int vrow = ks * 16 + vRowOf;
                const uint32_t va = kb + 16384 + vrow * 128 +
                                    (((2 * np + vCb) ^ (vrow & 7)) << 4);
                uint32_t f[4];
                ldsm4t(f, va);              // Vh (transposed frag)
                mma16816(o[2 * np],     ph, f[0], f[1]);
                mma16816(o[2 * np + 1], ph, f[2], f[3]);
                mma16816(o[2 * np],     pl, f[0], f[1]);
                mma16816(o[2 * np + 1], pl, f[2], f[3]);
                ldsm4t(f, va + 8192);       // Vl
                mma16816(o[2 * np],     ph, f[0], f[1]);
                mma16816(o[2 * np + 1], ph, f[2], f[3]);
            }
        }
        __syncthreads();
        if (kt + 2 < SS / 64) {
            loadKV(kt + 2, sb + 32768 + (kt & 1) * 32768);
            CP_COMMIT();
        }
    }

    // ---- epilogue: normalize, write bf16 [hi|hi|lo] rows of A2 ----
    const float il0 = 1.f / l0, il1 = 1.f / l1;
    const int tok0 = b * SS + qt * 128 + wid * 16 + (lane >> 2);
    const int c0 = h * DH + (lane & 3) * 2;
#pragma unroll
    for (int t = 0; t < 8; t++) {
        const int c = c0 + t * 8;
        uint32_t hp, lp;
        split_pair(o[t][0] * il0, o[t][1] * il0, hp, lp);
        __nv_bfloat16* d0 = outs + (size_t)tok0 * KP + c;
        *(uint32_t*)(d0)          = hp;
        *(uint32_t*)(d0 + DD)     = hp;
        *(uint32_t*)(d0 + 2 * DD) = lp;
        split_pair(o[t][2] * il1, o[t][3] * il1, hp, lp);
        __nv_bfloat16* d1 = outs + (size_t)(tok0 + 8) * KP + c;
        *(uint32_t*)(d1)          = hp;
        *(uint32_t*)(d1 + DD)     = hp;
        *(uint32_t*)(d1 + 2 * DD) = lp;
    }
}

// ---------------------------------------------------------------------------
extern "C" void kernel_launch(void* const* d_in, const int* in_sizes, int n_in,
                              void* d_out, int out_size) {
    const float* x     = (const float*)d_in[0];   // [4,2048,1024]
    const float* w_in  = (const float*)d_in[1];   // [3072,1024]
    const float* w_out = (const float*)d_in[2];   // [1024,1024]
    const float* b_out = (const float*)d_in[3];   // [1024]
    float* out = (float*)d_out;                   // [4,2048,1024]

    __nv_bfloat16 *A1, *W1, *A2, *W2, *Qh, *Ql, *Kh, *Kl, *Vh, *Vl;
    cudaGetSymbolAddress((void**)&A1, g_A1);
    cudaGetSymbolAddress((void**)&W1, g_W1);
    cudaGetSymbolAddress((void**)&A2, g_A2);
    cudaGetSymbolAddress((void**)&W2, g_W2);
    cudaGetSymbolAddress((void**)&Qh, g_Qh);
    cudaGetSymbolAddress((void**)&Ql, g_Ql);
    cudaGetSymbolAddress((void**)&Kh, g_Kh);
    cudaGetSymbolAddress((void**)&Kl, g_Kl);
    cudaGetSymbolAddress((void**)&Vh, g_Vh);
    cudaGetSymbolAddress((void**)&Vl, g_Vl);

    static int attr_set = 0;
    if (!attr_set) {
        cudaFuncSetAttribute(gemm_mma,
                             cudaFuncAttributeMaxDynamicSharedMemorySize, GSMEM);
        cudaFuncSetAttribute(flash_mma,
                             cudaFuncAttributeMaxDynamicSharedMemorySize, FSMEM);
        attr_set = 1;
    }

    const int rowsX = BB * SS;          // 8192
    split3<<<(rowsX * (DD / 4) + 255) / 256, 256>>>(x, A1, rowsX, 2);
    split3<<<(3 * DD * (DD / 4) + 255) / 256, 256>>>(w_in, W1, 3 * DD, 1);
    split3<<<(DD * (DD / 4) + 255) / 256, 256>>>(w_out, W2, DD, 1);

    // 1) QKV projection -> per-head split Q/K/V (no fp32 intermediate)
    gemm_mma<<<dim3(3 * DD / 128, rowsX / 128), 256, GSMEM>>>(
        A1, W1, nullptr, nullptr, 3 * DD, 1, Qh, Ql, Kh, Kl, Vh, Vl);

    // 2) attention on mma.sync -> bf16x3 activation rows
    flash_mma<<<dim3(SS / 128, HH, BB), 256, FSMEM>>>(
        Qh, Ql, Kh, Kl, Vh, Vl, A2);

    // 3) output projection + bias
    gemm_mma<<<dim3(DD / 128, rowsX / 128), 256, GSMEM>>>(
        A2, W2, b_out, out, DD, 0,
        nullptr, nullptr, nullptr, nullptr, nullptr, nullptr);
}

// round 9
// speedup vs baseline: 4.5706x; 1.1722x over previous
#include <cuda_runtime.h>
#include <cuda_bf16.h>
#include <cstdint>
#include <math.h>

#define BB 4
#define SS 2048
#define DD 1024
#define HH 16
#define DH 64
#define KP 3072            // split-K: 3 * DD
#define NITER (KP / 64)    // 48 chunks of 64 bf16

// ---------------------------------------------------------------------------
// Scratch (__device__ globals: allocation-free rule)
// ---------------------------------------------------------------------------
__device__ __nv_bfloat16 g_A1[(size_t)BB * SS * KP];        // x split    [hi|hi|lo]
__device__ __nv_bfloat16 g_W1[(size_t)3 * DD * KP];         // w_in split [hi|lo|hi]
__device__ __nv_bfloat16 g_A2[(size_t)BB * SS * KP];        // attn out   [hi|hi|lo]
__device__ __nv_bfloat16 g_W2[(size_t)DD * KP];             // w_out      [hi|lo|hi]
// per-head split QKV: [b][h][s][64]
__device__ __nv_bfloat16 g_Qh[(size_t)BB * HH * SS * DH];
__device__ __nv_bfloat16 g_Ql[(size_t)BB * HH * SS * DH];
__device__ __nv_bfloat16 g_Kh[(size_t)BB * HH * SS * DH];
__device__ __nv_bfloat16 g_Kl[(size_t)BB * HH * SS * DH];
__device__ __nv_bfloat16 g_Vh[(size_t)BB * HH * SS * DH];
__device__ __nv_bfloat16 g_Vl[(size_t)BB * HH * SS * DH];

// ---------------------------------------------------------------------------
// family-safe PTX helpers (sm_80+)
// ---------------------------------------------------------------------------
__device__ __forceinline__ uint32_t smem_to_u32(const void* p) {
    uint32_t a;
    asm("{ .reg .u64 t; cvta.to.shared.u64 t, %1; cvt.u32.u64 %0, t; }"
        : "=r"(a) : "l"(p));
    return a;
}
#define CP_ASYNC16(dst, src) \
    asm volatile("cp.async.cg.shared.global [%0], [%1], 16;\n" \
                 :: "r"(dst), "l"(src))
#define CP_COMMIT() asm volatile("cp.async.commit_group;\n" ::: "memory")
#define CP_WAIT(n)  asm volatile("cp.async.wait_group %0;\n" :: "n"(n) : "memory")

__device__ __forceinline__ void ldsm4(uint32_t& r0, uint32_t& r1,
                                      uint32_t& r2, uint32_t& r3, uint32_t addr) {
    asm volatile("ldmatrix.sync.aligned.m8n8.x4.shared.b16 {%0,%1,%2,%3}, [%4];\n"
                 : "=r"(r0), "=r"(r1), "=r"(r2), "=r"(r3) : "r"(addr));
}
__device__ __forceinline__ void ldsm4t(uint32_t* r, uint32_t addr) {
    asm volatile("ldmatrix.sync.aligned.m8n8.x4.trans.shared.b16 {%0,%1,%2,%3}, [%4];\n"
                 : "=r"(r[0]), "=r"(r[1]), "=r"(r[2]), "=r"(r[3]) : "r"(addr));
}
__device__ __forceinline__ void mma16816(float* c, const uint32_t* a,
                                         uint32_t b0, uint32_t b1) {
    asm volatile(
        "mma.sync.aligned.m16n8k16.row.col.f32.bf16.bf16.f32 "
        "{%0,%1,%2,%3}, {%4,%5,%6,%7}, {%8,%9}, {%0,%1,%2,%3};\n"
        : "+f"(c[0]), "+f"(c[1]), "+f"(c[2]), "+f"(c[3])
        : "r"(a[0]), "r"(a[1]), "r"(a[2]), "r"(a[3]), "r"(b0), "r"(b1));
}
__device__ __forceinline__ float exp2a(float x) {
    float r; asm("ex2.approx.f32 %0, %1;" : "=f"(r) : "f"(x)); return r;
}
// split (x0,x1) into packed bf16x2 hi + lo residual (lo halves of pair = x0)
__device__ __forceinline__ void split_pair(float x0, float x1,
                                           uint32_t& hi, uint32_t& lo) {
    uint32_t hp;
    asm("cvt.rn.bf16x2.f32 %0, %1, %2;" : "=r"(hp) : "f"(x1), "f"(x0));
    const float h0 = __uint_as_float(hp << 16);
    const float h1 = __uint_as_float(hp & 0xFFFF0000u);
    uint32_t lp;
    asm("cvt.rn.bf16x2.f32 %0, %1, %2;" : "=r"(lp) : "f"(x1 - h1), "f"(x0 - h0));
    hi = hp; lo = lp;
}
__device__ __forceinline__ uint32_t pk_bf2(__nv_bfloat16 a, __nv_bfloat16 b) {
    __nv_bfloat162 t; t.x = a; t.y = b;
    return *reinterpret_cast<uint32_t*>(&t);
}

// ---------------------------------------------------------------------------
// fp32 -> bf16x3 split (GEMM inputs). loSlot 1 = weights [hi|lo|hi],
// loSlot 2 = activations [hi|hi|lo].
// ---------------------------------------------------------------------------
__global__ void split3(const float* __restrict__ src, __nv_bfloat16* __restrict__ dst,
                       int rows, int loSlot) {
    int idx = blockIdx.x * blockDim.x + threadIdx.x;
    int total = rows * (DD / 4);
    if (idx >= total) return;
    int row = idx / (DD / 4);
    int c4  = (idx % (DD / 4)) * 4;
    float4 v = *(const float4*)(src + (size_t)row * DD + c4);
    float vv[4] = {v.x, v.y, v.z, v.w};
    __nv_bfloat16 h[4], l[4];
#pragma unroll
    for (int i = 0; i < 4; i++) {
        h[i] = __float2bfloat16_rn(vv[i]);
        l[i] = __float2bfloat16_rn(vv[i] - __bfloat162float(h[i]));
    }
    uint2 Hv = make_uint2(pk_bf2(h[0], h[1]), pk_bf2(h[2], h[3]));
    uint2 Lv = make_uint2(pk_bf2(l[0], l[1]), pk_bf2(l[2], l[3]));
    __nv_bfloat16* d0 = dst + (size_t)row * KP + c4;
    *(uint2*)(d0)          = Hv;
    *(uint2*)(d0 + DD)     = (loSlot == 1) ? Lv : Hv;
    *(uint2*)(d0 + 2 * DD) = (loSlot == 2) ? Lv : Hv;
}

// ---------------------------------------------------------------------------
// bf16 GEMM via mma.sync:  C = A'[M,KP] @ W'[Ntot,KP]^T
// 128x128 tile/CTA, 8 warps (64x32 warp tiles), BK=64.
// 3-stage cp.async pipeline, ONE __syncthreads per iteration, 2 CTAs/SM.
// splitMode 0: C fp32 (+bias).  splitMode 1: per-head split Q/K/V scatter.
// ---------------------------------------------------------------------------
#define GSTAGE_BYTES 32768
#define GSMEM (3 * GSTAGE_BYTES)   // 98304
#define QSC 0.18033688011112042f   // 0.125 * log2(e)

__global__ __launch_bounds__(256, 2)
void gemm_mma(const __nv_bfloat16* __restrict__ A,
              const __nv_bfloat16* __restrict__ Bw,
              const float* __restrict__ bias,
              float* __restrict__ C, int Ntot, int splitMode,
              __nv_bfloat16* __restrict__ Qh, __nv_bfloat16* __restrict__ Ql,
              __nv_bfloat16* __restrict__ Kh, __nv_bfloat16* __restrict__ Kl,
              __nv_bfloat16* __restrict__ Vh, __nv_bfloat16* __restrict__ Vl) {
    extern __shared__ char smem[];
    const uint32_t sb = smem_to_u32(smem);
    const int tid = threadIdx.x;
    const int lane = tid & 31, wid = tid >> 5;
    const int wm = wid & 1, wn = wid >> 1;          // 2 x 4 warp grid
    const int m0 = blockIdx.y * 128;
    const int n0 = blockIdx.x * 128;

    const int lrow  = tid >> 1;
    const int jbase = (tid & 1) * 4;
    uint32_t soff[4];
#pragma unroll
    for (int j = 0; j < 4; j++)
        soff[j] = (uint32_t)lrow * 128 + (uint32_t)(((jbase + j) ^ (lrow & 7)) << 4);
    const char* gA = (const char*)(A  + (size_t)(m0 + lrow) * KP) + jbase * 16;
    const char* gB = (const char*)(Bw + (size_t)(n0 + lrow) * KP) + jbase * 16;

    float acc[4][4][4];
#pragma unroll
    for (int mt = 0; mt < 4; mt++)
#pragma unroll
        for (int nt = 0; nt < 4; nt++)
#pragma unroll
            for (int e = 0; e < 4; e++) acc[mt][nt][e] = 0.f;

    const int a_row = wm * 64 + (lane & 15);
    const int a_cb  = lane >> 4;
    const int b_rowb = wn * 32 + (lane & 7) + ((lane >> 4) << 3);
    const int b_cb   = (lane >> 3) & 1;

    // --- prologue: fill stages 0,1 ---
#pragma unroll
    for (int pi = 0; pi < 2; pi++) {
        const uint32_t base = sb + pi * GSTAGE_BYTES;
#pragma unroll
        for (int j = 0; j < 4; j++) {
            CP_ASYNC16(base + soff[j],         gA + (size_t)pi * 128 + j * 16);
            CP_ASYNC16(base + 16384 + soff[j], gB + (size_t)pi * 128 + j * 16);
        }
        CP_COMMIT();
    }

    int stage = 0, nstage = 2;
    for (int i = 0; i < NITER; i++) {
        if (i + 1 < NITER) { CP_WAIT(1); } else { CP_WAIT(0); }
        __syncthreads();

        const uint32_t aBase = sb + stage * GSTAGE_BYTES;
        const uint32_t bBase = aBase + 16384;
#pragma unroll
        for (int ks = 0; ks < 4; ks++) {
            uint32_t af[4][4], bf[2][4];
#pragma unroll
            for (int mt = 0; mt < 4; mt++) {
                const int row = a_row + mt * 16;
                const uint32_t addr =
                    aBase + row * 128 + (((ks * 2 + a_cb) ^ (row & 7)) << 4);
                ldsm4(af[mt][0], af[mt][1], af[mt][2], af[mt][3], addr);
            }
#pragma unroll
            for (int p = 0; p < 2; p++) {
                const int row = b_rowb + p * 16;
                const uint32_t addr =
                    bBase + row * 128 + (((ks * 2 + b_cb) ^ (row & 7)) << 4);
                ldsm4(bf[p][0], bf[p][1], bf[p][2], bf[p][3], addr);
            }
#pragma unroll
            for (int mt = 0; mt < 4; mt++)
#pragma unroll
                for (int nt = 0; nt < 4; nt++)
                    mma16816(acc[mt][nt], af[mt],
                             bf[nt >> 1][(nt & 1) * 2], bf[nt >> 1][(nt & 1) * 2 + 1]);
        }

        // issue loads for chunk i+2 into stage (i+2)%3 == the stage consumed
        // at iter i-1; ordered by this iteration's barrier.
        if (i + 2 < NITER) {
            const uint32_t base = sb + nstage * GSTAGE_BYTES;
#pragma unroll
            for (int j = 0; j < 4; j++) {
                CP_ASYNC16(base + soff[j],         gA + (size_t)(i + 2) * 128 + j * 16);
                CP_ASYNC16(base + 16384 + soff[j], gB + (size_t)(i + 2) * 128 + j * 16);
            }
            CP_COMMIT();
        }
        stage  = (stage == 2)  ? 0 : stage + 1;
        nstage = (nstage == 2) ? 0 : nstage + 1;
    }

    if (splitMode) {
        // scatter into per-head hi/lo split arrays
#pragma unroll
        for (int mt = 0; mt < 4; mt++) {
            const int r = m0 + wm * 64 + mt * 16 + (lane >> 2);
#pragma unroll
            for (int nt = 0; nt < 4; nt++) {
                const int c = n0 + wn * 32 + nt * 8 + (lane & 3) * 2;
                const int sel = c >> 10;
                const int hh  = (c >> 6) & 15;
                const int d   = c & 63;
                __nv_bfloat16* dH = (sel == 0) ? Qh : (sel == 1) ? Kh : Vh;
                __nv_bfloat16* dL = (sel == 0) ? Ql : (sel == 1) ? Kl : Vl;
                const float sc = (sel == 0) ? QSC : 1.f;
#pragma unroll
                for (int hr = 0; hr < 2; hr++) {
                    const int row = r + hr * 8;
                    const int bb = row >> 11, ss = row & 2047;
                    const size_t idx =
                        (((size_t)(bb * HH + hh)) * SS + ss) * DH + d;
                    uint32_t hp, lp;
                    split_pair(acc[mt][nt][hr * 2] * sc,
                               acc[mt][nt][hr * 2 + 1] * sc, hp, lp);
                    *(uint32_t*)(dH + idx) = hp;
                    *(uint32_t*)(dL + idx) = lp;
                }
            }
        }
    } else {
#pragma unroll
        for (int mt = 0; mt < 4; mt++) {
            const int r = m0 + wm * 64 + mt * 16 + (lane >> 2);
#pragma unroll
            for (int nt = 0; nt < 4; nt++) {
                const int c = n0 + wn * 32 + nt * 8 + (lane & 3) * 2;
                float2 v0 = make_float2(acc[mt][nt][0], acc[mt][nt][1]);
                float2 v1 = make_float2(acc[mt][nt][2], acc[mt][nt][3]);
                if (bias) {
                    const float b0v = bias[c], b1v = bias[c + 1];
                    v0.x += b0v; v0.y += b1v;
                    v1.x += b0v; v1.y += b1v;
                }
                *(float2*)(C + (size_t)r * Ntot + c)       = v0;
                *(float2*)(C + (size_t)(r + 8) * Ntot + c) = v1;
            }
        }
    }
}

// ---------------------------------------------------------------------------
// Flash attention on mma.sync. Br=128, Bc=64, 8 warps.
// S = Qh*Kh + Ql*Kh + Qh*Kl ; O = Ph*Vh + Pl*Vh + Ph*Vl (bf16x3 both stages).
// Q pre-scaled by 0.125*log2e -> softmax via ex2.approx.
// smem: Qh 16K | Ql 16K | 2 x KV buf (Kh 8K | Kl 8K | Vh 8K | Vl 8K)
// ---------------------------------------------------------------------------
#define FSMEM 98304

__global__ __launch_bounds__(256, 2)
void flash_mma(const __nv_bfloat16* __restrict__ Qh, const __nv_bfloat16* __restrict__ Ql,
               const __nv_bfloat16* __restrict__ Kh, const __nv_bfloat16* __restrict__ Kl,
               const __nv_bfloat16* __restrict__ Vh, const __nv_bfloat16* __restrict__ Vl,
               __nv_bfloat16* __restrict__ outs) {
    extern __shared__ char smem[];
    const uint32_t sb = smem_to_u32(smem);
    const int tid = threadIdx.x, lane = tid & 31, wid = tid >> 5;
    const int qt = blockIdx.x, h = blockIdx.y, b = blockIdx.z;
    const size_t gq = ((size_t)(b * HH + h) * SS + (size_t)qt * 128) * DH;
    const size_t gk = (size_t)(b * HH + h) * SS * DH;

    // --- Q load: 128 rows x 8 chunks, hi + lo ---
    {
        const int row = tid >> 1;
        const int cb = (tid & 1) * 4;
        const char* ph = (const char*)(Qh + gq + (size_t)row * DH);
        const char* pl = (const char*)(Ql + gq + (size_t)row * DH);
#pragma unroll
        for (int j = 0; j < 4; j++) {
            const int ch = cb + j;
            const uint32_t so = row * 128 + ((ch ^ (row & 7)) << 4);
            CP_ASYNC16(sb + so,         ph + ch * 16);
            CP_ASYNC16(sb + 16384 + so, pl + ch * 16);
        }
    }
    const int kvrow = tid >> 2;
    const int kvcb  = (tid & 3) * 2;
    auto loadKV = [&](int kt, uint32_t bufb) {
        const size_t ro = gk + (size_t)(kt * 64 + kvrow) * DH;
#pragma unroll
        for (int j = 0; j < 2; j++) {
            const int ch = kvcb + j;
            const uint32_t so = kvrow * 128 + ((ch ^ (kvrow & 7)) << 4);
            CP_ASYNC16(bufb + so,         (const char*)(Kh + ro) + ch * 16);
            CP_ASYNC16(bufb + 8192 + so,  (const char*)(Kl + ro) + ch * 16);
            CP_ASYNC16(bufb + 16384 + so, (const char*)(Vh + ro) + ch * 16);
            CP_ASYNC16(bufb + 24576 + so, (const char*)(Vl + ro) + ch * 16);
        }
    };
    loadKV(0, sb + 32768); CP_COMMIT();
    loadKV(1, sb + 65536); CP_COMMIT();

    float s[8][4], o[8][4];
    float m0 = -100000.f, m1 = -100000.f, l0 = 0.f, l1 = 0.f;
#pragma unroll
    for (int t = 0; t < 8; t++)
#pragma unroll
        for (int e = 0; e < 4; e++) o[t][e] = 0.f;

    const int aRow   = wid * 16 + (lane & 15);
    const int aCb    = lane >> 4;
    const int kRowOf = (lane & 7) + ((lane >> 4) << 3);
    const int kCb    = (lane >> 3) & 1;
    const int vRowOf = (lane & 7) + (((lane >> 3) & 1) << 3);
    const int vCb    = lane >> 4;

    for (int kt = 0; kt < SS / 64; kt++) {
        if (kt + 2 < SS / 64) { CP_WAIT(1); } else { CP_WAIT(0); }
        __syncthreads();
        const uint32_t kb = sb + 32768 + (kt & 1) * 32768;

#pragma unroll
        for (int t = 0; t < 8; t++)
#pragma unroll
            for (int e = 0; e < 4; e++) s[t][e] = 0.f;

        // ---- S = Q*K^T (3 terms) ----
#pragma unroll
        for (int ks = 0; ks < 4; ks++) {
            uint32_t qf[4], ql[4];
            const uint32_t qa =
                sb + aRow * 128 + (((2 * ks + aCb) ^ (aRow & 7)) << 4);
            ldsm4(qf[0], qf[1], qf[2], qf[3], qa);
            ldsm4(ql[0], ql[1], ql[2], ql[3], qa + 16384);
#pragma unroll
            for (int np = 0; np < 4; np++) {
                const int krow = np * 16 + kRowOf;
                const uint32_t ka =
                    kb + krow * 128 + (((2 * ks + kCb) ^ (krow & 7)) << 4);
                uint32_t f[4];
                ldsm4(f[0], f[1], f[2], f[3], ka);          // Kh
                mma16816(s[2 * np],     qf, f[0], f[1]);
                mma16816(s[2 * np + 1], qf, f[2], f[3]);
                mma16816(s[2 * np],     ql, f[0], f[1]);
                mma16816(s[2 * np + 1], ql, f[2], f[3]);
                ldsm4(f[0], f[1], f[2], f[3], ka + 8192);   // Kl
                mma16816(s[2 * np],     qf, f[0], f[1]);
                mma16816(s[2 * np + 1], qf, f[2], f[3]);
            }
        }

        // ---- online softmax (rows r=lane>>2 and r+8) ----
        {
            float mx = fmaxf(s[0][0], s[0][1]);
#pragma unroll
            for (int t = 1; t < 8; t++) mx = fmaxf(mx, fmaxf(s[t][0], s[t][1]));
            mx = fmaxf(mx, __shfl_xor_sync(0xffffffffu, mx, 1));
            mx = fmaxf(mx, __shfl_xor_sync(0xffffffffu, mx, 2));
            const float mn = fmaxf(m0, mx);
            const float al = exp2a(m0 - mn);
            float sum = 0.f;
#pragma unroll
            for (int t = 0; t < 8; t++) {
                s[t][0] = exp2a(s[t][0] - mn);
                s[t][1] = exp2a(s[t][1] - mn);
                sum += s[t][0] + s[t][1];
            }
            sum += __shfl_xor_sync(0xffffffffu, sum, 1);
            sum += __shfl_xor_sync(0xffffffffu, sum, 2);
            l0 = l0 * al + sum; m0 = mn;
#pragma unroll
            for (int t = 0; t < 8; t++) { o[t][0] *= al; o[t][1] *= al; }
        }
        {
            float mx = fmaxf(s[0][2], s[0][3]);
#pragma unroll
            for (int t = 1; t < 8; t++) mx = fmaxf(mx, fmaxf(s[t][2], s[t][3]));
            mx = fmaxf(mx, __shfl_xor_sync(0xffffffffu, mx, 1));
            mx = fmaxf(mx, __shfl_xor_sync(0xffffffffu, mx, 2));
            const float mn = fmaxf(m1, mx);
            const float al = exp2a(m1 - mn);
            float sum = 0.f;
#pragma unroll
            for (int t = 0; t < 8; t++) {
                s[t][2] = exp2a(s[t][2] - mn);
                s[t][3] = exp2a(s[t][3] - mn);
                sum += s[t][2] + s[t][3];
            }
            sum += __shfl_xor_sync(0xffffffffu, sum, 1);
            sum += __shfl_xor_sync(0xffffffffu, sum, 2);
            l1 = l1 * al + sum; m1 = mn;
#pragma unroll
            for (int t = 0; t < 8; t++) { o[t][2] *= al; o[t][3] *= al; }
        }

        // ---- O += P*V (3 terms); P frags built in-register from S ----
#pragma unroll
        for (int ks = 0; ks < 4; ks++) {
            uint32_t ph[4], pl[4];
            split_pair(s[2 * ks][0],     s[2 * ks][1],     ph[0], pl[0]);
            split_pair(s[2 * ks][2],     s[2 * ks][3],     ph[1], pl[1]);
            split_pair(s[2 * ks + 1][0], s[2 * ks + 1][1], ph[2], pl[2]);
            split_pair(s[2 * ks + 1][2], s[2 * ks + 1][3], ph[3], pl[3]);
#pragma unroll
            for (int np = 0; np < 4; np++) {
                const int vrow = ks * 16 + vRowOf;
                const uint32_t va = kb + 16384 + vrow * 128 +
                                    (((2 * np + vCb) ^ (vrow & 7)) << 4);
                uint32_t f[4];
                ldsm4t(f, va);              // Vh (transposed frag)
                mma16816(o[2 * np],     ph, f[0], f[1]);
                mma16816(o[2 * np + 1], ph, f[2], f[3]);
                mma16816(o[2 * np],     pl, f[0], f[1]);
                mma16816(o[2 * np + 1], pl, f[2], f[3]);
                ldsm4t(f, va + 8192);       // Vl
                mma16816(o[2 * np],     ph, f[0], f[1]);
                mma16816(o[2 * np + 1], ph, f[2], f[3]);
            }
        }
        __syncthreads();
        if (kt + 2 < SS / 64) {
            loadKV(kt + 2, sb + 32768 + (kt & 1) * 32768);
            CP_COMMIT();
        }
    }

    // ---- epilogue: normalize, write bf16 [hi|hi|lo] rows of A2 ----
    const float il0 = 1.f / l0, il1 = 1.f / l1;
    const int tok0 = b * SS + qt * 128 + wid * 16 + (lane >> 2);
    const int c0 = h * DH + (lane & 3) * 2;
#pragma unroll
    for (int t = 0; t < 8; t++) {
        const int c = c0 + t * 8;
        uint32_t hp, lp;
        split_pair(o[t][0] * il0, o[t][1] * il0, hp, lp);
        __nv_bfloat16* d0 = outs + (size_t)tok0 * KP + c;
        *(uint32_t*)(d0)          = hp;
        *(uint32_t*)(d0 + DD)     = hp;
        *(uint32_t*)(d0 + 2 * DD) = lp;
        split_pair(o[t][2] * il1, o[t][3] * il1, hp, lp);
        __nv_bfloat16* d1 = outs + (size_t)(tok0 + 8) * KP + c;
        *(uint32_t*)(d1)          = hp;
        *(uint32_t*)(d1 + DD)     = hp;
        *(uint32_t*)(d1 + 2 * DD) = lp;
    }
}

// ---------------------------------------------------------------------------
extern "C" void kernel_launch(void* const* d_in, const int* in_sizes, int n_in,
                              void* d_out, int out_size) {
    const float* x     = (const float*)d_in[0];   // [4,2048,1024]
    const float* w_in  = (const float*)d_in[1];   // [3072,1024]
    const float* w_out = (const float*)d_in[2];   // [1024,1024]
    const float* b_out = (const float*)d_in[3];   // [1024]
    float* out = (float*)d_out;                   // [4,2048,1024]

    __nv_bfloat16 *A1, *W1, *A2, *W2, *Qh, *Ql, *Kh, *Kl, *Vh, *Vl;
    cudaGetSymbolAddress((void**)&A1, g_A1);
    cudaGetSymbolAddress((void**)&W1, g_W1);
    cudaGetSymbolAddress((void**)&A2, g_A2);
    cudaGetSymbolAddress((void**)&W2, g_W2);
    cudaGetSymbolAddress((void**)&Qh, g_Qh);
    cudaGetSymbolAddress((void**)&Ql, g_Ql);
    cudaGetSymbolAddress((void**)&Kh, g_Kh);
    cudaGetSymbolAddress((void**)&Kl, g_Kl);
    cudaGetSymbolAddress((void**)&Vh, g_Vh);
    cudaGetSymbolAddress((void**)&Vl, g_Vl);

    static int attr_set = 0;
    if (!attr_set) {
        cudaFuncSetAttribute(gemm_mma,
                             cudaFuncAttributeMaxDynamicSharedMemorySize, GSMEM);
        cudaFuncSetAttribute(flash_mma,
                             cudaFuncAttributeMaxDynamicSharedMemorySize, FSMEM);
        attr_set = 1;
    }

    const int rowsX = BB * SS;          // 8192
    split3<<<(rowsX * (DD / 4) + 255) / 256, 256>>>(x, A1, rowsX, 2);
    split3<<<(3 * DD * (DD / 4) + 255) / 256, 256>>>(w_in, W1, 3 * DD, 1);
    split3<<<(DD * (DD / 4) + 255) / 256, 256>>>(w_out, W2, DD, 1);

    // 1) QKV projection -> per-head split Q/K/V (no fp32 intermediate)
    gemm_mma<<<dim3(3 * DD / 128, rowsX / 128), 256, GSMEM>>>(
        A1, W1, nullptr, nullptr, 3 * DD, 1, Qh, Ql, Kh, Kl, Vh, Vl);

    // 2) attention on mma.sync -> bf16x3 activation rows
    flash_mma<<<dim3(SS / 128, HH, BB), 256, FSMEM>>>(
        Qh, Ql, Kh, Kl, Vh, Vl, A2);

    // 3) output projection + bias
    gemm_mma<<<dim3(DD / 128, rowsX / 128), 256, GSMEM>>>(
        A2, W2, b_out, out, DD, 0,
        nullptr, nullptr, nullptr, nullptr, nullptr, nullptr);
}